// round 2
// baseline (speedup 1.0000x reference)
#include <cuda_runtime.h>
#include <math.h>
#include <stdint.h>

#define T_STEPS 512
#define BATCH   1024
#define HID     64
#define G4      256          // 4*H gate columns
#define B_TILE  8
#define NTHREADS 512

// Inter-layer scratch (allocation-free rule: __device__ globals)
__device__ float g_buf0[BATCH * T_STEPS * HID];   // 128 MB
__device__ float g_buf1[BATCH * T_STEPS * HID];   // 128 MB
__device__ float g_hlast[BATCH * HID];

__device__ __forceinline__ float sigf(float x) {
    return __fdividef(1.0f, 1.0f + __expf(-x));
}
__device__ __forceinline__ float tanh_fast(float x) {
    float t = fabsf(x);
    float e = __expf(-2.0f * t);
    float r = __fdividef(1.0f - e, 1.0f + e);
    return copysignf(r, x);
}

__device__ __forceinline__ uint64_t pack2(float lo, float hi) {
    uint64_t r;
    asm("mov.b64 %0, {%1, %2};" : "=l"(r) : "f"(lo), "f"(hi));
    return r;
}
__device__ __forceinline__ void unpack2(uint64_t v, float& lo, float& hi) {
    asm("mov.b64 {%0, %1}, %2;" : "=f"(lo), "=f"(hi) : "l"(v));
}
// d = a * b + d, two packed fp32 lanes (Blackwell FFMA2)
__device__ __forceinline__ void ffma2(uint64_t& d, uint64_t a, uint64_t b) {
    asm("fma.rn.f32x2 %0, %1, %2, %0;" : "+l"(d) : "l"(a), "l"(b));
}

// One CTA = 8 batch elements, 512 threads.
// Thread t: unit u = t>>3 (0..63), batch b = t&7. Computes 4 gates for (u,b)
// as 2 packed-f32x2 accumulators: (i,f) and (g,o).
// Smem: W_s[k][unit*4+gate] fp32 (k in [0,IN_W)=w_ih cols, [IN_W,K)=w_hh cols),
//       xh2[k][b] = float2(v,v)  (DUPLICATED so f32x2 a-operand needs no pack).
template <int IN_W, bool LAST_ONLY>
__global__ void __launch_bounds__(NTHREADS)
lstm_layer(const float* __restrict__ x,     // [B][T][IN_W]
           const float* __restrict__ w_ih,  // [256][IN_W]
           const float* __restrict__ w_hh,  // [256][64]
           const float* __restrict__ b_ih,  // [256]
           const float* __restrict__ b_hh,  // [256]
           float* __restrict__ y)           // [B][T][64] or [B][64] if LAST_ONLY
{
    constexpr int K = IN_W + HID;
    extern __shared__ float smem[];
    float*  W_s = smem;                     // K * 256 floats
    float2* xh2 = (float2*)(W_s + K * G4);  // K * 8 float2 (duplicated)

    const int tid = threadIdx.x;
    const int b0  = blockIdx.x * B_TILE;
    const int u   = tid >> 3;   // hidden unit
    const int b   = tid & 7;    // batch within tile

    // ---- cooperative weight load + reorder: W_s[k*256 + un*4 + gt] ----
    for (int idx = tid; idx < K * G4; idx += NTHREADS) {
        int k  = idx / G4;
        int cp = idx % G4;            // unit*4 + gate
        int un = cp >> 2, gt = cp & 3;
        int r  = gt * HID + un;       // original row: gate-major
        W_s[idx] = (k < IN_W) ? w_ih[r * IN_W + k]
                              : w_hh[r * HID + (k - IN_W)];
    }
    // per-thread packed biases for unit u
    uint64_t bias01, bias23;
    {
        float bi = b_ih[0 * HID + u] + b_hh[0 * HID + u];
        float bf = b_ih[1 * HID + u] + b_hh[1 * HID + u];
        float bg = b_ih[2 * HID + u] + b_hh[2 * HID + u];
        float bo = b_ih[3 * HID + u] + b_hh[3 * HID + u];
        bias01 = pack2(bi, bf);
        bias23 = pack2(bg, bo);
    }
    // h_{-1} = 0 (duplicated slots)
    {
        int v = tid;                  // exactly 512 = HID*B_TILE slots
        xh2[IN_W * B_TILE + v] = make_float2(0.0f, 0.0f);
    }
    // x_0 (duplicated)
    for (int v = tid; v < IN_W * B_TILE; v += NTHREADS) {
        int bb = v / IN_W, k = v % IN_W;
        float val = x[((size_t)(b0 + bb) * T_STEPS + 0) * IN_W + k];
        xh2[k * B_TILE + bb] = make_float2(val, val);
    }
    float c = 0.0f;
    __syncthreads();

    const ulonglong2* W2 = (const ulonglong2*)W_s;  // [K][64] : .x=(w0,w1) .y=(w2,w3)
    const uint64_t*   XH = (const uint64_t*)xh2;    // [K][8]  : duplicated pair

    for (int t = 0; t < T_STEPS; t++) {
        uint64_t a01 = bias01;   // (i, f)
        uint64_t a23 = bias23;   // (g, o)
#pragma unroll 8
        for (int k = 0; k < K; k++) {
            ulonglong2 w = W2[k * 64 + u];
            uint64_t  xv = XH[k * 8 + b];
            ffma2(a01, xv, w.x);
            ffma2(a23, xv, w.y);
        }
        float gi, gf, gg, go;
        unpack2(a01, gi, gf);
        unpack2(a23, gg, go);
        float iv = sigf(gi), fv = sigf(gf), gv = tanh_fast(gg), ov = sigf(go);
        c = fv * c + iv * gv;
        float h = ov * tanh_fast(c);

        __syncthreads();   // all xh reads for step t complete

        xh2[(IN_W + u) * B_TILE + b] = make_float2(h, h);

        if (!LAST_ONLY) {
            y[((size_t)(b0 + b) * T_STEPS + t) * HID + u] = h;
        } else if (t == T_STEPS - 1) {
            y[(size_t)(b0 + b) * HID + u] = h;
        }

        if (t + 1 < T_STEPS) {
            for (int v = tid; v < IN_W * B_TILE; v += NTHREADS) {
                int bb, k;
                if (IN_W == 64) { bb = v >> 6; k = v & 63; }
                else            { bb = v / IN_W; k = v % IN_W; }
                float val = x[((size_t)(b0 + bb) * T_STEPS + (t + 1)) * IN_W + k];
                xh2[k * B_TILE + bb] = make_float2(val, val);
            }
        }
        __syncthreads();   // new xh ready
    }
}

// MLP head: z = relu(h@fc1^T+b1); z = relu(z@fc3^T+b3); out = z@fc2^T+b2
__global__ void __launch_bounds__(256)
head_kernel(const float* __restrict__ hlast,
            const float* __restrict__ fc1_w, const float* __restrict__ fc1_b,
            const float* __restrict__ fc3_w, const float* __restrict__ fc3_b,
            const float* __restrict__ fc2_w, const float* __restrict__ fc2_b,
            float* __restrict__ out)
{
    __shared__ float h_s[8][64];
    __shared__ float z1_s[8][128];
    __shared__ float z2_s[8][64];
    const int tid = threadIdx.x;
    const int b0  = blockIdx.x * 8;

    for (int v = tid; v < 8 * 64; v += 256)
        h_s[v >> 6][v & 63] = hlast[(size_t)(b0 + (v >> 6)) * 64 + (v & 63)];
    __syncthreads();

    for (int v = tid; v < 8 * 128; v += 256) {
        int bb = v >> 7, j = v & 127;
        float s = fc1_b[j];
#pragma unroll 8
        for (int k = 0; k < 64; k++) s += h_s[bb][k] * fc1_w[j * 64 + k];
        z1_s[bb][j] = fmaxf(s, 0.0f);
    }
    __syncthreads();

    for (int v = tid; v < 8 * 64; v += 256) {
        int bb = v >> 6, j = v & 63;
        float s = fc3_b[j];
#pragma unroll 8
        for (int k = 0; k < 128; k++) s += z1_s[bb][k] * fc3_w[j * 128 + k];
        z2_s[bb][j] = fmaxf(s, 0.0f);
    }
    __syncthreads();

    if (tid < 16) {
        int bb = tid >> 1, j = tid & 1;
        float s = fc2_b[j];
#pragma unroll
        for (int k = 0; k < 64; k++) s += z2_s[bb][k] * fc2_w[j * 64 + k];
        out[(b0 + bb) * 2 + j] = s;
    }
}

extern "C" void kernel_launch(void* const* d_in, const int* in_sizes, int n_in,
                              void* d_out, int out_size)
{
    const float* x     = (const float*)d_in[0];
    const float* w_ih0 = (const float*)d_in[1];
    const float* w_hh0 = (const float*)d_in[2];
    const float* b_ih0 = (const float*)d_in[3];
    const float* b_hh0 = (const float*)d_in[4];
    const float* w_ih1 = (const float*)d_in[5];
    const float* w_hh1 = (const float*)d_in[6];
    const float* b_ih1 = (const float*)d_in[7];
    const float* b_hh1 = (const float*)d_in[8];
    const float* w_ih2 = (const float*)d_in[9];
    const float* w_hh2 = (const float*)d_in[10];
    const float* b_ih2 = (const float*)d_in[11];
    const float* b_hh2 = (const float*)d_in[12];
    const float* fc1_w = (const float*)d_in[13];
    const float* fc1_b = (const float*)d_in[14];
    const float* fc3_w = (const float*)d_in[15];
    const float* fc3_b = (const float*)d_in[16];
    const float* fc2_w = (const float*)d_in[17];
    const float* fc2_b = (const float*)d_in[18];
    float* out = (float*)d_out;

    float *buf0 = nullptr, *buf1 = nullptr, *hlast = nullptr;
    cudaGetSymbolAddress((void**)&buf0,  g_buf0);
    cudaGetSymbolAddress((void**)&buf1,  g_buf1);
    cudaGetSymbolAddress((void**)&hlast, g_hlast);

    // dynamic smem: weights (K*256 f32) + duplicated xh (K*8 float2)
    const int SMEM_L0  = (70  * G4 + 70  * B_TILE * 2) * (int)sizeof(float); //  76160
    const int SMEM_L12 = (128 * G4 + 128 * B_TILE * 2) * (int)sizeof(float); // 139264

    cudaFuncSetAttribute((const void*)lstm_layer<6,  false>,
                         cudaFuncAttributeMaxDynamicSharedMemorySize, SMEM_L0);
    cudaFuncSetAttribute((const void*)lstm_layer<64, false>,
                         cudaFuncAttributeMaxDynamicSharedMemorySize, SMEM_L12);
    cudaFuncSetAttribute((const void*)lstm_layer<64, true>,
                         cudaFuncAttributeMaxDynamicSharedMemorySize, SMEM_L12);

    const int GRID = BATCH / B_TILE;   // 128

    lstm_layer<6,  false><<<GRID, NTHREADS, SMEM_L0 >>>(x,    w_ih0, w_hh0, b_ih0, b_hh0, buf0);
    lstm_layer<64, false><<<GRID, NTHREADS, SMEM_L12>>>(buf0, w_ih1, w_hh1, b_ih1, b_hh1, buf1);
    lstm_layer<64, true ><<<GRID, NTHREADS, SMEM_L12>>>(buf1, w_ih2, w_hh2, b_ih2, b_hh2, hlast);
    head_kernel<<<GRID, 256>>>(hlast, fc1_w, fc1_b, fc3_w, fc3_b, fc2_w, fc2_b, out);
}

// round 3
// speedup vs baseline: 1.8258x; 1.8258x over previous
#include <cuda_runtime.h>
#include <math.h>
#include <stdint.h>

#define T_STEPS 512
#define BATCH   1024
#define HID     64
#define G4      256
#define B_TILE  8
#define NT      256

__device__ float g_buf0[BATCH * T_STEPS * HID];   // layer0 -> layer1
__device__ float g_buf1[BATCH * T_STEPS * HID];   // layer1 -> layer2

__device__ __forceinline__ float sigf(float x) {
    return __fdividef(1.0f, 1.0f + __expf(-x));
}
__device__ __forceinline__ float tanh_fast(float x) {
    float t = fabsf(x);
    float e = __expf(-2.0f * t);
    float r = __fdividef(1.0f - e, 1.0f + e);
    return copysignf(r, x);
}
__device__ __forceinline__ uint64_t pack2(float lo, float hi) {
    uint64_t r; asm("mov.b64 %0, {%1, %2};" : "=l"(r) : "f"(lo), "f"(hi)); return r;
}
__device__ __forceinline__ void unpack2(uint64_t v, float& lo, float& hi) {
    asm("mov.b64 {%0, %1}, %2;" : "=f"(lo), "=f"(hi) : "l"(v));
}
// d += a * b, two packed fp32 lanes (Blackwell FFMA2)
__device__ __forceinline__ void ffma2(uint64_t& d, uint64_t a, uint64_t b) {
    asm("fma.rn.f32x2 %0, %1, %2, %0;" : "+l"(d) : "l"(a), "l"(b));
}

// One CTA = 8 batch elements, 256 threads.
// GEMM phase: thread = gate column c = tid (c = u*4+gate). Weights for that
// column live in registers as K/2 packed (w[2k],w[2k+1]) pairs. Activations
// xh[k2][b] = (xh[2k2],xh[2k2+1]) for batch b are broadcast-read from smem.
// Accumulator acc[b] lanes = (even-k partial, odd-k partial); horizontal add at end.
// Epilogue phase: thread = (unit u_e = tid&63, batch-pair bp_e = tid>>6).
template <int IN_W, bool LAST>
__global__ void __launch_bounds__(NT, 1)
lstm_layer(const float* __restrict__ x,     // [B][T][IN_W]
           const float* __restrict__ w_ih,  // [256][IN_W]
           const float* __restrict__ w_hh,  // [256][64]
           const float* __restrict__ b_ih,
           const float* __restrict__ b_hh,
           float* __restrict__ y,           // [B][T][64], or out[B][2] if LAST
           const float* __restrict__ fc1_w, const float* __restrict__ fc1_b,
           const float* __restrict__ fc3_w, const float* __restrict__ fc3_b,
           const float* __restrict__ fc2_w, const float* __restrict__ fc2_b)
{
    constexpr int K  = IN_W + HID;
    constexpr int K2 = K / 2;
    extern __shared__ uint64_t smem[];
    uint64_t* xh  = smem;                     // [K2][8] packed k-pairs per batch
    float2*   gs  = (float2*)(xh + K2 * 8);   // [4][256] gate staging
    float*   head = (float*)(gs + 4 * G4);    // LAST only

    const int tid = threadIdx.x;
    const int b0  = blockIdx.x * B_TILE;

    // ---- weights -> registers (one time) ----
    const int u  = tid >> 2;
    const int gt = tid & 3;                   // 0:i 1:f 2:g 3:o
    const int r  = gt * HID + u;              // original gate-major row
    uint64_t w2[K2];
#pragma unroll
    for (int k2 = 0; k2 < K2; k2++) {
        int k = 2 * k2;
        float w0, w1;
        if (k < IN_W) { w0 = w_ih[r * IN_W + k];         w1 = w_ih[r * IN_W + k + 1]; }
        else          { w0 = w_hh[r * HID + (k - IN_W)]; w1 = w_hh[r * HID + (k - IN_W) + 1]; }
        w2[k2] = pack2(w0, w1);
    }
    const float bias = b_ih[r] + b_hh[r];

    // ---- init: zero h region (k2 in [IN_W/2, K2)), load x(0) ----
    xh[(IN_W / 2 + (tid >> 3)) * 8 + (tid & 7)] = 0ull;   // 32*8 slots, one per thread
    if (IN_W == 64) {
        int b = tid >> 5, l = tid & 31;
        float2 v = *(const float2*)(x + ((size_t)(b0 + b) * T_STEPS + 0) * IN_W + 2 * l);
        xh[l * 8 + b] = pack2(v.x, v.y);
    } else {
        if (tid < (IN_W / 2) * 8) {
            int k2 = tid >> 3, b = tid & 7;
            float2 v = *(const float2*)(x + ((size_t)(b0 + b) * T_STEPS + 0) * IN_W + 2 * k2);
            xh[k2 * 8 + b] = pack2(v.x, v.y);
        }
    }
    __syncthreads();

    const ulonglong2* XH2 = (const ulonglong2*)xh;
    const int u_e = tid & 63, bp_e = tid >> 6;
    float c0 = 0.0f, c1 = 0.0f;

    for (int t = 0; t < T_STEPS; t++) {
        // prefetch x(t+1) into registers (hidden under the k-loop)
        float2 xpre = make_float2(0.f, 0.f);
        if (t + 1 < T_STEPS) {
            if (IN_W == 64) {
                int b = tid >> 5, l = tid & 31;
                xpre = *(const float2*)(x + ((size_t)(b0 + b) * T_STEPS + (t + 1)) * IN_W + 2 * l);
            } else if (tid < (IN_W / 2) * 8) {
                int k2 = tid >> 3, b = tid & 7;
                xpre = *(const float2*)(x + ((size_t)(b0 + b) * T_STEPS + (t + 1)) * IN_W + 2 * k2);
            }
        }

        // ---- gate GEMM: 8 batches, this thread's column ----
        uint64_t acc[8];
#pragma unroll
        for (int j = 0; j < 8; j++) acc[j] = 0ull;
#pragma unroll
        for (int k2 = 0; k2 < K2; k2++) {
            ulonglong2 a0 = XH2[k2 * 4 + 0];   // batches 0,1
            ulonglong2 a1 = XH2[k2 * 4 + 1];   // batches 2,3
            ulonglong2 a2 = XH2[k2 * 4 + 2];   // batches 4,5
            ulonglong2 a3 = XH2[k2 * 4 + 3];   // batches 6,7
            uint64_t w = w2[k2];
            ffma2(acc[0], a0.x, w); ffma2(acc[1], a0.y, w);
            ffma2(acc[2], a1.x, w); ffma2(acc[3], a1.y, w);
            ffma2(acc[4], a2.x, w); ffma2(acc[5], a2.y, w);
            ffma2(acc[6], a3.x, w); ffma2(acc[7], a3.y, w);
        }
#pragma unroll
        for (int bp = 0; bp < 4; bp++) {
            float e0, o0, e1, o1;
            unpack2(acc[2 * bp],     e0, o0);
            unpack2(acc[2 * bp + 1], e1, o1);
            gs[bp * G4 + tid] = make_float2(bias + e0 + o0, bias + e1 + o1);
        }
        __syncthreads();

        // ---- epilogue: c/h update for (u_e, batches 2*bp_e, 2*bp_e+1) ----
        {
            const float2* gp = gs + bp_e * G4 + 4 * u_e;
            float2 vi = gp[0], vf = gp[1], vg = gp[2], vo = gp[3];
            float i0 = sigf(vi.x), f0 = sigf(vf.x), g0 = tanh_fast(vg.x), o0 = sigf(vo.x);
            float i1 = sigf(vi.y), f1 = sigf(vf.y), g1 = tanh_fast(vg.y), o1 = sigf(vo.y);
            c0 = f0 * c0 + i0 * g0;
            c1 = f1 * c1 + i1 * g1;
            float h0 = o0 * tanh_fast(c0);
            float h1 = o1 * tanh_fast(c1);
            // write h into broadcast buffer at k = IN_W + u_e
            float* xf = (float*)xh;
            int k    = IN_W + u_e;
            int base = (k >> 1) * 16 + 4 * bp_e + (k & 1);
            xf[base]     = h0;
            xf[base + 2] = h1;
            if (!LAST) {
                y[((size_t)(b0 + 2 * bp_e)     * T_STEPS + t) * HID + u_e] = h0;
                y[((size_t)(b0 + 2 * bp_e + 1) * T_STEPS + t) * HID + u_e] = h1;
            } else if (t == T_STEPS - 1) {
                head[(2 * bp_e)     * HID + u_e] = h0;
                head[(2 * bp_e + 1) * HID + u_e] = h1;
            }
        }
        // store prefetched x(t+1)
        if (t + 1 < T_STEPS) {
            if (IN_W == 64) {
                int b = tid >> 5, l = tid & 31;
                xh[l * 8 + b] = pack2(xpre.x, xpre.y);
            } else if (tid < (IN_W / 2) * 8) {
                int k2 = tid >> 3, b = tid & 7;
                xh[k2 * 8 + b] = pack2(xpre.x, xpre.y);
            }
        }
        __syncthreads();
    }

    // ---- fused MLP head (LAST layer only) ----
    if (LAST) {
        float* h_s = head;            // 512 floats  [8][64]
        float* z1  = head + 512;      // 1024        [8][128]
        float* z2  = head + 1536;     // 512         [8][64]
        float* wf1 = head + 2048;     // 8192        fc1_w staged
        float* wf3 = head + 10240;    // 8192        fc3_w staged
        for (int i = tid; i < 128 * 64; i += NT) wf1[i] = fc1_w[i];
        for (int i = tid; i < 64 * 128; i += NT) wf3[i] = fc3_w[i];
        __syncthreads();
        for (int v = tid; v < 8 * 128; v += NT) {
            int b = v >> 7, j = v & 127;
            float s = fc1_b[j];
#pragma unroll 8
            for (int k = 0; k < 64; k++) s += h_s[b * 64 + k] * wf1[j * 64 + k];
            z1[b * 128 + j] = fmaxf(s, 0.0f);
        }
        __syncthreads();
        for (int v = tid; v < 8 * 64; v += NT) {
            int b = v >> 6, j = v & 63;
            float s = fc3_b[j];
#pragma unroll 8
            for (int k = 0; k < 128; k++) s += z1[b * 128 + k] * wf3[j * 128 + k];
            z2[b * 64 + j] = fmaxf(s, 0.0f);
        }
        __syncthreads();
        if (tid < 16) {
            int b = tid >> 1, j = tid & 1;
            float s = fc2_b[j];
#pragma unroll
            for (int k = 0; k < 64; k++) s += z2[b * 64 + k] * fc2_w[j * 64 + k];
            y[(b0 + b) * 2 + j] = s;
        }
    }
}

extern "C" void kernel_launch(void* const* d_in, const int* in_sizes, int n_in,
                              void* d_out, int out_size)
{
    const float* x     = (const float*)d_in[0];
    const float* w_ih0 = (const float*)d_in[1];
    const float* w_hh0 = (const float*)d_in[2];
    const float* b_ih0 = (const float*)d_in[3];
    const float* b_hh0 = (const float*)d_in[4];
    const float* w_ih1 = (const float*)d_in[5];
    const float* w_hh1 = (const float*)d_in[6];
    const float* b_ih1 = (const float*)d_in[7];
    const float* b_hh1 = (const float*)d_in[8];
    const float* w_ih2 = (const float*)d_in[9];
    const float* w_hh2 = (const float*)d_in[10];
    const float* b_ih2 = (const float*)d_in[11];
    const float* b_hh2 = (const float*)d_in[12];
    const float* fc1_w = (const float*)d_in[13];
    const float* fc1_b = (const float*)d_in[14];
    const float* fc3_w = (const float*)d_in[15];
    const float* fc3_b = (const float*)d_in[16];
    const float* fc2_w = (const float*)d_in[17];
    const float* fc2_b = (const float*)d_in[18];
    float* out = (float*)d_out;

    float *buf0 = nullptr, *buf1 = nullptr;
    cudaGetSymbolAddress((void**)&buf0, g_buf0);
    cudaGetSymbolAddress((void**)&buf1, g_buf1);

    // dynamic smem: xh (K2*8 u64) + gs (4*256 float2) [+ head region for LAST]
    const int SM_L0 = 35 * 8 * 8 + 4 * G4 * 8;                 // 10432
    const int SM_L1 = 64 * 8 * 8 + 4 * G4 * 8;                 // 12288
    const int SM_L2 = SM_L1 + (512 + 1024 + 512 + 8192 + 8192) * 4;  // 86016

    cudaFuncSetAttribute((const void*)lstm_layer<6,  false>,
                         cudaFuncAttributeMaxDynamicSharedMemorySize, SM_L0);
    cudaFuncSetAttribute((const void*)lstm_layer<64, false>,
                         cudaFuncAttributeMaxDynamicSharedMemorySize, SM_L1);
    cudaFuncSetAttribute((const void*)lstm_layer<64, true>,
                         cudaFuncAttributeMaxDynamicSharedMemorySize, SM_L2);

    const int GRID = BATCH / B_TILE;   // 128

    lstm_layer<6,  false><<<GRID, NT, SM_L0>>>(x,    w_ih0, w_hh0, b_ih0, b_hh0, buf0,
                                               nullptr, nullptr, nullptr, nullptr, nullptr, nullptr);
    lstm_layer<64, false><<<GRID, NT, SM_L1>>>(buf0, w_ih1, w_hh1, b_ih1, b_hh1, buf1,
                                               nullptr, nullptr, nullptr, nullptr, nullptr, nullptr);
    lstm_layer<64, true ><<<GRID, NT, SM_L2>>>(buf1, w_ih2, w_hh2, b_ih2, b_hh2, out,
                                               fc1_w, fc1_b, fc3_w, fc3_b, fc2_w, fc2_b);
}